// round 7
// baseline (speedup 1.0000x reference)
#include <cuda_runtime.h>

// Density loss via exact KNN (k=16, self included) on [8, 2048, 3] clouds.
//
// Kernel A: sort each of the 16 clouds by x once (bitonic, in-block), write
//           sorted (x,y,z,|p|^2) to global scratch.
// Kernel B: each warp owns 32 consecutive sorted points. Seed top-16 from the
//           3 nearest batches, derive an exact conservative x-window from the
//           seeded threshold (binary search), then scan only that window with
//           a warp-ballot screen in front of the 206-op sort/merge network.
//           Final reduction + MSE folded in via last-block counter.

#define B 8
#define N 2048
#define KNN 16
#define CLOUDS 16                 // 2 tensors * 8 batches
#define SORT_THREADS 512
#define SCAN_THREADS 128
#define CHUNKS 16                 // 16 chunks of 128 points per cloud
#define SCAN_BLOCKS (CLOUDS * CHUNKS)   // 256

__device__ float4 g_sorted[CLOUDS * N];
__device__ float g_partial[SCAN_BLOCKS];
__device__ int g_count = 0;

// compare-exchange: x <- min, y <- max
#define CE(x, y) { float _lo = fminf((x), (y)); (y) = fmaxf((x), (y)); (x) = _lo; }

// Sort 16 candidates (Batcher, 63 CE), keep 16 smallest of (a U c) via
// bitonic min-step, restore sortedness of a with a 32-CE bitonic cleanup.
__device__ __forceinline__ void merge_batch(float (&a)[KNN], float (&c)[KNN], float& t) {
    CE(c[0], c[1]) CE(c[2], c[3]) CE(c[0], c[2]) CE(c[1], c[3]) CE(c[1], c[2])
    CE(c[4], c[5]) CE(c[6], c[7]) CE(c[4], c[6]) CE(c[5], c[7]) CE(c[5], c[6])
    CE(c[0], c[4]) CE(c[2], c[6]) CE(c[2], c[4])
    CE(c[1], c[5]) CE(c[3], c[7]) CE(c[3], c[5])
    CE(c[1], c[2]) CE(c[3], c[4]) CE(c[5], c[6])
    CE(c[8], c[9]) CE(c[10], c[11]) CE(c[8], c[10]) CE(c[9], c[11]) CE(c[9], c[10])
    CE(c[12], c[13]) CE(c[14], c[15]) CE(c[12], c[14]) CE(c[13], c[15]) CE(c[13], c[14])
    CE(c[8], c[12]) CE(c[10], c[14]) CE(c[10], c[12])
    CE(c[9], c[13]) CE(c[11], c[15]) CE(c[11], c[13])
    CE(c[9], c[10]) CE(c[11], c[12]) CE(c[13], c[14])
    CE(c[0], c[8])  CE(c[4], c[12]) CE(c[4], c[8])
    CE(c[2], c[10]) CE(c[6], c[14]) CE(c[6], c[10])
    CE(c[2], c[4])  CE(c[6], c[8])  CE(c[10], c[12])
    CE(c[1], c[9])  CE(c[5], c[13]) CE(c[5], c[9])
    CE(c[3], c[11]) CE(c[7], c[15]) CE(c[7], c[11])
    CE(c[3], c[5])  CE(c[7], c[9])  CE(c[11], c[13])
    CE(c[1], c[2]) CE(c[3], c[4]) CE(c[5], c[6]) CE(c[7], c[8])
    CE(c[9], c[10]) CE(c[11], c[12]) CE(c[13], c[14])

#pragma unroll
    for (int q = 0; q < KNN; ++q) a[q] = fminf(a[q], c[15 - q]);

#pragma unroll
    for (int q = 0; q < 8; ++q) CE(a[q], a[q + 8])
    CE(a[0], a[4]) CE(a[1], a[5]) CE(a[2], a[6]) CE(a[3], a[7])
    CE(a[8], a[12]) CE(a[9], a[13]) CE(a[10], a[14]) CE(a[11], a[15])
    CE(a[0], a[2]) CE(a[1], a[3]) CE(a[4], a[6]) CE(a[5], a[7])
    CE(a[8], a[10]) CE(a[9], a[11]) CE(a[12], a[14]) CE(a[13], a[15])
    CE(a[0], a[1]) CE(a[2], a[3]) CE(a[4], a[5]) CE(a[6], a[7])
    CE(a[8], a[9]) CE(a[10], a[11]) CE(a[12], a[13]) CE(a[14], a[15])

    t = a[15];
}

// ---------------- Kernel A: sort each cloud by x (once) ----------------
__global__ __launch_bounds__(SORT_THREADS)
void sort_kernel(const float* __restrict__ seed, const float* __restrict__ gt_s) {
    __shared__ unsigned long long key[N];   // 16 KB

    const int cloud  = blockIdx.x;          // 0..15
    const int tensor = cloud >> 3;
    const int batch  = cloud & 7;
    const int tid    = threadIdx.x;

    const float* __restrict__ src =
        (tensor == 0 ? seed : gt_s) + (size_t)batch * N * 3;

    for (int i = tid; i < N; i += SORT_THREADS) {
        unsigned u = __float_as_uint(src[3 * i]);
        u = (u & 0x80000000u) ? ~u : (u | 0x80000000u);
        key[i] = ((unsigned long long)u << 32) | (unsigned)i;
    }

    for (int k = 2; k <= N; k <<= 1) {
        for (int j = k >> 1; j > 0; j >>= 1) {
            __syncthreads();
            for (int i = tid; i < N; i += SORT_THREADS) {
                int l = i ^ j;
                if (l > i) {
                    unsigned long long u0 = key[i], u1 = key[l];
                    if ((u0 > u1) == ((i & k) == 0)) { key[i] = u1; key[l] = u0; }
                }
            }
        }
    }
    __syncthreads();

    float4* __restrict__ dst = g_sorted + (size_t)cloud * N;
    for (int i = tid; i < N; i += SORT_THREADS) {
        int idx = (int)(key[i] & 0xffffffffu);
        float x = src[3 * idx], y = src[3 * idx + 1], z = src[3 * idx + 2];
        dst[i] = make_float4(x, y, z, x * x + y * y + z * z);
    }
}

// ---------------- Kernel B: windowed exact top-16 scan ----------------
__device__ __forceinline__ void batch_dist(const float4* __restrict__ spts, int base,
                                           float ai, float mx, float my, float mz,
                                           float (&c)[16]) {
#pragma unroll
    for (int q = 0; q < 16; ++q) {
        float4 s = spts[base + q];
        float d = ai + s.w;
        d = fmaf(mx, s.x, d);
        d = fmaf(my, s.y, d);
        d = fmaf(mz, s.z, d);
        c[q] = d;
    }
}

__global__ __launch_bounds__(SCAN_THREADS)
void scan_kernel(float* __restrict__ out) {
    __shared__ float4 spts[N];              // 32 KB, sorted by x
    __shared__ float red[SCAN_THREADS];
    __shared__ float dd[CLOUDS];
    __shared__ int last;

    const int bx    = blockIdx.x;           // 0..255
    const int cloud = bx >> 4;
    const int chunk = bx & 15;
    const int tid   = threadIdx.x;

    const float4* __restrict__ gs = g_sorted + (size_t)cloud * N;
    for (int i = tid; i < N; i += SCAN_THREADS) spts[i] = gs[i];
    __syncthreads();

    const int myp       = chunk * SCAN_THREADS + tid;
    const int warp_base = myp & ~31;

    const float4 xi = spts[myp];
    const float ai = xi.w;
    const float mx = -2.0f * xi.x;
    const float my = -2.0f * xi.y;
    const float mz = -2.0f * xi.z;

    float a[KNN];
#pragma unroll
    for (int q = 0; q < KNN; ++q) a[q] = 3.4e38f;
    float t = 3.4e38f;

    // ---- seed: 3 nearest batches (48 candidates incl. self), full merges ----
    int s0 = warp_base - 16;
    if (s0 < 0) s0 = 0;
    if (s0 > N - 48) s0 = N - 48;
#pragma unroll
    for (int s = 0; s < 3; ++s) {
        float c[16];
        batch_dist(spts, s0 + 16 * s, ai, mx, my, mz, c);
        merge_batch(a, c, t);
    }

    // ---- exact conservative window from seeded t (warp-uniform) ----
    float r = sqrtf(t);
    float xlo = xi.x - r;
    float xhi = xi.x + r;
#pragma unroll
    for (int off = 16; off >= 1; off >>= 1) {
        xlo = fminf(xlo, __shfl_xor_sync(0xffffffffu, xlo, off));
        xhi = fmaxf(xhi, __shfl_xor_sync(0xffffffffu, xhi, off));
    }

    // first index with x >= xlo
    int lo = 0, hi = N;
    while (lo < hi) { int mid = (lo + hi) >> 1; if (spts[mid].x < xlo) lo = mid + 1; else hi = mid; }
    const int lo_idx = lo;
    // first index with x > xhi
    lo = 0; hi = N;
    while (lo < hi) { int mid = (lo + hi) >> 1; if (spts[mid].x <= xhi) lo = mid + 1; else hi = mid; }
    const int hi_idx = lo;   // exclusive

    // ---- windowed scan with ballot screen ----
    for (int base = lo_idx & ~15; base < hi_idx; base += 16) {
        if (base == s0 || base == s0 + 16 || base == s0 + 32) continue;
        float c[16];
        batch_dist(spts, base, ai, mx, my, mz, c);
        float m0 = fminf(fminf(fminf(c[0], c[1]), fminf(c[2], c[3])),
                         fminf(fminf(c[4], c[5]), fminf(c[6], c[7])));
        float m1 = fminf(fminf(fminf(c[8], c[9]), fminf(c[10], c[11])),
                         fminf(fminf(c[12], c[13]), fminf(c[14], c[15])));
        if (__ballot_sync(0xffffffffu, fminf(m0, m1) < t))
            merge_batch(a, c, t);
    }

    // ---- per-point mean of 16 nearest ----
    float s16 = 0.0f;
#pragma unroll
    for (int q = 0; q < KNN; ++q) s16 += a[q];
    float point_mean = s16 * (1.0f / KNN);

    // ---- block reduction ----
    red[tid] = point_mean;
    __syncthreads();
#pragma unroll
    for (int stride = SCAN_THREADS / 2; stride > 0; stride >>= 1) {
        if (tid < stride) red[tid] += red[tid + stride];
        __syncthreads();
    }
    if (tid == 0) g_partial[bx] = red[0];

    // ---- last-block finalize ----
    __threadfence();
    if (tid == 0) last = (atomicAdd(&g_count, 1) == SCAN_BLOCKS - 1);
    __syncthreads();
    if (last) {
        if (tid < CLOUDS) {
            float s = 0.0f;
#pragma unroll
            for (int c2 = 0; c2 < CHUNKS; ++c2)
                s += __ldcg(&g_partial[tid * CHUNKS + c2]);
            dd[tid] = s * (1.0f / N);
        }
        __syncthreads();
        if (tid == 0) {
            float loss = 0.0f;
#pragma unroll
            for (int b = 0; b < B; ++b) {
                float df = dd[b] - dd[B + b];
                loss += df * df;
            }
            out[0] = loss * (1.0f / B);
            g_count = 0;   // reset for next graph replay
        }
    }
}

extern "C" void kernel_launch(void* const* d_in, const int* in_sizes, int n_in,
                              void* d_out, int out_size) {
    const float* seed = (const float*)d_in[0];
    const float* gt_s = (const float*)d_in[1];
    float* out = (float*)d_out;

    sort_kernel<<<CLOUDS, SORT_THREADS>>>(seed, gt_s);
    scan_kernel<<<SCAN_BLOCKS, SCAN_THREADS>>>(out);
}

// round 9
// speedup vs baseline: 1.2701x; 1.2701x over previous
#include <cuda_runtime.h>

// Density loss via exact KNN (k=16, self included) on [8, 2048, 3] clouds.
//
// Kernel A (16 blocks): counting bucket-sort each cloud by x into 256 uniform
//   buckets (O(N): minmax + histogram + scan + scatter). Writes bucketed
//   (x,y,z,|p|^2) float4s + bucket start table + (xmin,scale) per cloud.
// Kernel B (256 blocks x 256 thr): each 32-query group is served by a PAIR of
//   warps (even/odd candidate batches of the same x-window). Seed top-16 from
//   the 3 batches around the query group -> threshold t_seed -> exact
//   conservative x-window via O(1) bucket lookup. Scan with warp-ballot screen
//   in front of the 206-FMNMX sort/merge network. Warp pairs merge via smem.
//   Reduction + MSE folded in with a last-block counter.

#define B 8
#define N 2048
#define KNN 16
#define CLOUDS 16
#define NB 256                    // x-buckets per cloud
#define SORT_THREADS 256
#define SCAN_THREADS 256          // 8 warps: 4 query-groups x 2 parities
#define CHUNKS 16                 // 128 queries per scan block
#define SCAN_BLOCKS (CLOUDS * CHUNKS)   // 256

__device__ float4 g_sorted[CLOUDS * N];
__device__ int    g_bstart[CLOUDS][NB + 1];
__device__ float2 g_cinfo[CLOUDS];      // (xmin, scale)
__device__ float  g_partial[SCAN_BLOCKS];
__device__ int    g_count = 0;

#define CE(x, y) { float _lo = fminf((x), (y)); (y) = fmaxf((x), (y)); (x) = _lo; }

// keep 16 smallest of two ascending lists a, c (c consumed reversed), result ascending
__device__ __forceinline__ void merge_sorted16(float (&a)[KNN], const float (&c)[KNN]) {
#pragma unroll
    for (int q = 0; q < KNN; ++q) a[q] = fminf(a[q], c[15 - q]);
    // a is bitonic: 4-stage cleanup
#pragma unroll
    for (int q = 0; q < 8; ++q) CE(a[q], a[q + 8])
    CE(a[0], a[4]) CE(a[1], a[5]) CE(a[2], a[6]) CE(a[3], a[7])
    CE(a[8], a[12]) CE(a[9], a[13]) CE(a[10], a[14]) CE(a[11], a[15])
    CE(a[0], a[2]) CE(a[1], a[3]) CE(a[4], a[6]) CE(a[5], a[7])
    CE(a[8], a[10]) CE(a[9], a[11]) CE(a[12], a[14]) CE(a[13], a[15])
    CE(a[0], a[1]) CE(a[2], a[3]) CE(a[4], a[5]) CE(a[6], a[7])
    CE(a[8], a[9]) CE(a[10], a[11]) CE(a[12], a[13]) CE(a[14], a[15])
}

// Batcher sort of 16 candidates (63 CE) then fold into sorted a
__device__ __forceinline__ void merge_batch(float (&a)[KNN], float (&c)[KNN], float& t) {
    CE(c[0], c[1]) CE(c[2], c[3]) CE(c[0], c[2]) CE(c[1], c[3]) CE(c[1], c[2])
    CE(c[4], c[5]) CE(c[6], c[7]) CE(c[4], c[6]) CE(c[5], c[7]) CE(c[5], c[6])
    CE(c[0], c[4]) CE(c[2], c[6]) CE(c[2], c[4])
    CE(c[1], c[5]) CE(c[3], c[7]) CE(c[3], c[5])
    CE(c[1], c[2]) CE(c[3], c[4]) CE(c[5], c[6])
    CE(c[8], c[9]) CE(c[10], c[11]) CE(c[8], c[10]) CE(c[9], c[11]) CE(c[9], c[10])
    CE(c[12], c[13]) CE(c[14], c[15]) CE(c[12], c[14]) CE(c[13], c[15]) CE(c[13], c[14])
    CE(c[8], c[12]) CE(c[10], c[14]) CE(c[10], c[12])
    CE(c[9], c[13]) CE(c[11], c[15]) CE(c[11], c[13])
    CE(c[9], c[10]) CE(c[11], c[12]) CE(c[13], c[14])
    CE(c[0], c[8])  CE(c[4], c[12]) CE(c[4], c[8])
    CE(c[2], c[10]) CE(c[6], c[14]) CE(c[6], c[10])
    CE(c[2], c[4])  CE(c[6], c[8])  CE(c[10], c[12])
    CE(c[1], c[9])  CE(c[5], c[13]) CE(c[5], c[9])
    CE(c[3], c[11]) CE(c[7], c[15]) CE(c[7], c[11])
    CE(c[3], c[5])  CE(c[7], c[9])  CE(c[11], c[13])
    CE(c[1], c[2]) CE(c[3], c[4]) CE(c[5], c[6]) CE(c[7], c[8])
    CE(c[9], c[10]) CE(c[11], c[12]) CE(c[13], c[14])

    merge_sorted16(a, c);
    t = a[15];
}

// ---------------- Kernel A: counting bucket-sort per cloud ----------------
__global__ __launch_bounds__(SORT_THREADS)
void bucket_kernel(const float* __restrict__ seed, const float* __restrict__ gt_s) {
    __shared__ float rmin[SORT_THREADS], rmax[SORT_THREADS];
    __shared__ int hist[NB];
    __shared__ int cursor[NB];

    const int cloud = blockIdx.x;
    const int tid   = threadIdx.x;
    const float* __restrict__ src =
        ((cloud >> 3) == 0 ? seed : gt_s) + (size_t)(cloud & 7) * N * 3;

    // min/max x
    float lmin = 3.4e38f, lmax = -3.4e38f;
    for (int i = tid; i < N; i += SORT_THREADS) {
        float x = src[3 * i];
        lmin = fminf(lmin, x);
        lmax = fmaxf(lmax, x);
    }
    rmin[tid] = lmin; rmax[tid] = lmax;
    __syncthreads();
    for (int s = SORT_THREADS / 2; s > 0; s >>= 1) {
        if (tid < s) {
            rmin[tid] = fminf(rmin[tid], rmin[tid + s]);
            rmax[tid] = fmaxf(rmax[tid], rmax[tid + s]);
        }
        __syncthreads();
    }
    const float xmin  = rmin[0];
    const float range = rmax[0] - xmin;
    const float scale = (float)NB / fmaxf(range * (1.0f + 1e-6f), 1e-30f);

    // histogram
    hist[tid] = 0;
    __syncthreads();
    for (int i = tid; i < N; i += SORT_THREADS) {
        int b = (int)((src[3 * i] - xmin) * scale);
        b = max(0, min(NB - 1, b));
        atomicAdd(&hist[b], 1);
    }
    __syncthreads();

    // inclusive Hillis-Steele scan over NB (== blockDim) entries
    int val = hist[tid];
    for (int off = 1; off < NB; off <<= 1) {
        int u = (tid >= off) ? hist[tid - off] : 0;
        __syncthreads();
        val += u;
        hist[tid] = val;
        __syncthreads();
    }
    int start = (tid == 0) ? 0 : hist[tid - 1];
    g_bstart[cloud][tid] = start;
    if (tid == 0) g_bstart[cloud][NB] = N;
    cursor[tid] = start;
    __syncthreads();

    // scatter
    float4* __restrict__ dst = g_sorted + (size_t)cloud * N;
    for (int i = tid; i < N; i += SORT_THREADS) {
        float x = src[3 * i], y = src[3 * i + 1], z = src[3 * i + 2];
        int b = (int)((x - xmin) * scale);
        b = max(0, min(NB - 1, b));
        int pos = atomicAdd(&cursor[b], 1);
        dst[pos] = make_float4(x, y, z, x * x + y * y + z * z);
    }
    if (tid == 0) g_cinfo[cloud] = make_float2(xmin, scale);
}

// ---------------- Kernel B: windowed exact top-16 scan ----------------
__device__ __forceinline__ void batch_dist(const float4* __restrict__ spts, int base,
                                           float ai, float mx, float my, float mz,
                                           float (&c)[16]) {
#pragma unroll
    for (int q = 0; q < 16; ++q) {
        float4 s = spts[base + q];
        float d = ai + s.w;
        d = fmaf(mx, s.x, d);
        d = fmaf(my, s.y, d);
        d = fmaf(mz, s.z, d);
        c[q] = d;
    }
}

__global__ __launch_bounds__(SCAN_THREADS)
void scan_kernel(float* __restrict__ out) {
    __shared__ float4 spts[N];               // 32 KB
    __shared__ int sbstart[NB + 1];
    __shared__ float odd_a[128][17];         // odd-parity results (+pad)
    __shared__ float red[128];
    __shared__ float dd[CLOUDS];
    __shared__ int last;

    const int bx    = blockIdx.x;
    const int cloud = bx >> 4;
    const int chunk = bx & 15;
    const int tid   = threadIdx.x;
    const int wid   = tid >> 5;
    const int lane  = tid & 31;
    const int qg    = wid >> 1;              // query group 0..3
    const int par   = wid & 1;               // candidate parity

    const float4* __restrict__ gs = g_sorted + (size_t)cloud * N;
    for (int i = tid; i < N; i += SCAN_THREADS) spts[i] = gs[i];
    for (int i = tid; i < NB + 1; i += SCAN_THREADS) sbstart[i] = g_bstart[cloud][i];
    const float2 ci = g_cinfo[cloud];
    __syncthreads();

    const int qbase = chunk * 128 + qg * 32;
    const int myp   = qbase + lane;

    const float4 xi = spts[myp];
    const float ai = xi.w;
    const float mx = -2.0f * xi.x;
    const float my = -2.0f * xi.y;
    const float mz = -2.0f * xi.z;

    float a[KNN];
#pragma unroll
    for (int q = 0; q < KNN; ++q) a[q] = 3.4e38f;
    float t = 3.4e38f;

    // ---- seed: 3 batches around the query group (48 cands incl. self) ----
    int s0 = qbase - 16;
    if (s0 < 0) s0 = 0;
    if (s0 > N - 48) s0 = N - 48;
#pragma unroll
    for (int s = 0; s < 3; ++s) {
        float c[16];
        batch_dist(spts, s0 + 16 * s, ai, mx, my, mz, c);
        merge_batch(a, c, t);
    }
    const float t_seed = t;

    // odd warp: drop seed candidates (even warp keeps them) so the pair's
    // union counts every candidate exactly once; screen with t_seed anyway.
    if (par) {
#pragma unroll
        for (int q = 0; q < KNN; ++q) a[q] = 3.4e38f;
        t = 3.4e38f;
    }

    // ---- exact conservative window (warp-uniform) ----
    float r = sqrtf(t_seed);
    float xlo = xi.x - r;
    float xhi = xi.x + r;
#pragma unroll
    for (int off = 16; off >= 1; off >>= 1) {
        xlo = fminf(xlo, __shfl_xor_sync(0xffffffffu, xlo, off));
        xhi = fmaxf(xhi, __shfl_xor_sync(0xffffffffu, xhi, off));
    }
    int b_lo = (int)((xlo - ci.x) * ci.y); b_lo = max(0, min(NB - 1, b_lo));
    int b_hi = (int)((xhi - ci.x) * ci.y); b_hi = max(0, min(NB - 1, b_hi));
    const int lo_idx = sbstart[b_lo];
    const int hi_idx = sbstart[b_hi + 1];

    // ---- parity-split windowed scan with ballot screen ----
    for (int base = (lo_idx & ~15) + 16 * par; base < hi_idx; base += 32) {
        if (base == s0 || base == s0 + 16 || base == s0 + 32) continue;
        float c[16];
        batch_dist(spts, base, ai, mx, my, mz, c);
        float m0 = fminf(fminf(fminf(c[0], c[1]), fminf(c[2], c[3])),
                         fminf(fminf(c[4], c[5]), fminf(c[6], c[7])));
        float m1 = fminf(fminf(fminf(c[8], c[9]), fminf(c[10], c[11])),
                         fminf(fminf(c[12], c[13]), fminf(c[14], c[15])));
        if (__ballot_sync(0xffffffffu, fminf(m0, m1) < fminf(t, t_seed)))
            merge_batch(a, c, t);
    }

    // ---- pair merge through smem ----
    if (par) {
#pragma unroll
        for (int q = 0; q < KNN; ++q) odd_a[qg * 32 + lane][q] = a[q];
    }
    __syncthreads();
    if (!par) {
        float c[16];
#pragma unroll
        for (int q = 0; q < KNN; ++q) c[q] = odd_a[qg * 32 + lane][q];
        merge_sorted16(a, c);
        float s16 = 0.0f;
#pragma unroll
        for (int q = 0; q < KNN; ++q) s16 += a[q];
        red[qg * 32 + lane] = s16 * (1.0f / KNN);
    }
    __syncthreads();

    // ---- block reduction over 128 query means ----
    for (int s = 64; s > 0; s >>= 1) {
        if (tid < s) red[tid] += red[tid + s];
        __syncthreads();
    }
    if (tid == 0) g_partial[bx] = red[0];

    // ---- last-block finalize ----
    __threadfence();
    if (tid == 0) last = (atomicAdd(&g_count, 1) == SCAN_BLOCKS - 1);
    __syncthreads();
    if (last) {
        if (tid < CLOUDS) {
            float s = 0.0f;
#pragma unroll
            for (int c2 = 0; c2 < CHUNKS; ++c2)
                s += __ldcg(&g_partial[tid * CHUNKS + c2]);
            dd[tid] = s * (1.0f / N);
        }
        __syncthreads();
        if (tid == 0) {
            float loss = 0.0f;
#pragma unroll
            for (int b = 0; b < B; ++b) {
                float df = dd[b] - dd[B + b];
                loss += df * df;
            }
            out[0] = loss * (1.0f / B);
            g_count = 0;   // reset for next graph replay
        }
    }
}

extern "C" void kernel_launch(void* const* d_in, const int* in_sizes, int n_in,
                              void* d_out, int out_size) {
    const float* seed = (const float*)d_in[0];
    const float* gt_s = (const float*)d_in[1];
    float* out = (float*)d_out;

    bucket_kernel<<<CLOUDS, SORT_THREADS>>>(seed, gt_s);
    scan_kernel<<<SCAN_BLOCKS, SCAN_THREADS>>>(out);
}